// round 14
// baseline (speedup 1.0000x reference)
#include <cuda_runtime.h>
#include <cuda_bf16.h>

#define NN 100000
#define NE 1600000
#define NG 512
#define F  128
#define NCONV 4
#define NB_SCAN 98   // (NN + 1023) / 1024

typedef unsigned int uint;

// ---------------- scratch (device globals; no allocation) ----------------
__device__ uint  g_xb[NN * (F / 2)];     // layer input x, packed bf16x2 (25.6MB)
__device__ uint  g_bufA[NN * (F / 2)];   // g = (x@W)*dinv[row], packed bf16x2
__device__ __nv_bfloat16 g_wtb[NCONV * F * F];  // W^T per layer, [l][c][k] bf16
__device__ int   g_cnt[NN];
__device__ int   g_rowptr[NN + 1];
__device__ int   g_cursor[NN];
__device__ int   g_csr[NE];
__device__ uint  g_stat[128];            // decoupled-lookback status words
__device__ float g_dinv[NN];
__device__ float g_gsum[NG * F];
__device__ float g_gcnt[NG];

// ---------------- init: zero cnt + scan flags + pool accumulators, one launch ----------------
__global__ void fill_init(int* __restrict__ cnt, uint* __restrict__ stat,
                          float* __restrict__ gsum, float* __restrict__ gcnt) {
    int i = blockIdx.x * blockDim.x + threadIdx.x;
    if (i < NN) cnt[i] = 0;
    if (i < 128) stat[i] = 0u;
    if (i < NG * F) gsum[i] = 0.f;
    if (i < NG) gcnt[i] = 0.f;
}

__global__ void count_kernel(const int* __restrict__ ei, int* __restrict__ cnt) {
    int e = blockIdx.x * blockDim.x + threadIdx.x;
    if (e < NE) atomicAdd(&cnt[ei[NE + e]], 1);
}

__device__ __forceinline__ uint pk_bf16x2(float lo, float hi) {
    uint r;
    asm("cvt.rn.bf16x2.f32 %0, %1, %2;" : "=r"(r) : "f"(hi), "f"(lo));
    return r;
}

// convert x0 -> packed bf16, and W -> W^T bf16, in one launch
__global__ void convert_all(const float* __restrict__ x, const float* __restrict__ W,
                            uint* __restrict__ xb, __nv_bfloat16* __restrict__ wtb) {
    int i = blockIdx.x * blockDim.x + threadIdx.x;
    if (i < NN * (F / 2)) {
        float2 v = reinterpret_cast<const float2*>(x)[i];
        xb[i] = pk_bf16x2(v.x, v.y);
    } else {
        int j = i - NN * (F / 2);
        if (j < NCONV * F * F) {
            int l = j >> 14, r = j & 16383, c = r >> 7, k = r & 127;
            wtb[j] = __float2bfloat16(W[(l << 14) + (k << 7) + c]);
        }
    }
}

// ---------------- single-pass scan (decoupled lookback) + dinv + cursor ----------------
__global__ void scan_lb(const int* __restrict__ cnt, int* __restrict__ rowptr,
                        float* __restrict__ dinv, int* __restrict__ cursor,
                        uint* __restrict__ stat) {
    __shared__ int s[1024];
    __shared__ int s_prefix;
    int bid = blockIdx.x;
    int tid = threadIdx.x;
    int i = bid * 1024 + tid;
    int v = (i < NN) ? cnt[i] : 0;
    if (i < NN) dinv[i] = rsqrtf((float)v + 2.0f);   // improved=True self-loop weight 2
    s[tid] = v;
    __syncthreads();
    #pragma unroll
    for (int off = 1; off < 1024; off <<= 1) {
        int t = (tid >= off) ? s[tid - off] : 0;
        __syncthreads();
        s[tid] += t;
        __syncthreads();
    }
    if (tid == 1023) {
        uint agg = (uint)s[1023];
        atomicExch(&stat[bid], agg | ((bid == 0 ? 2u : 1u) << 30));
    }
    if (bid == 0 && tid == 0) s_prefix = 0;
    if (bid > 0 && tid < 32) {
        int lane = tid;
        uint run = 0;
        int p = bid - 1;
        while (true) {
            int idx = p - lane;
            uint wv;
            if (idx >= 0) {
                do { wv = atomicAdd(&stat[idx], 0u); } while ((wv >> 30) == 0u);
            } else {
                wv = (2u << 30);
            }
            uint m2 = __ballot_sync(0xffffffffu, (wv >> 30) == 2u);
            if (m2) {
                int firstp = __ffs(m2) - 1;
                uint val = (lane <= firstp) ? (wv & 0x3fffffffu) : 0u;
                #pragma unroll
                for (int o = 16; o > 0; o >>= 1) val += __shfl_down_sync(0xffffffffu, val, o);
                if (lane == 0) run += val;
                break;
            } else {
                uint val = wv & 0x3fffffffu;
                #pragma unroll
                for (int o = 16; o > 0; o >>= 1) val += __shfl_down_sync(0xffffffffu, val, o);
                if (lane == 0) run += val;
                p -= 32;
            }
        }
        if (lane == 0) {
            s_prefix = (int)run;
            atomicExch(&stat[bid], (run + (uint)s[1023]) | (2u << 30));
        }
    }
    __syncthreads();
    int pre = s_prefix;
    if (i < NN) {
        int incl = pre + s[tid];
        rowptr[i + 1] = incl;
        cursor[i] = incl - v;
    }
    if (i == 0) rowptr[0] = 0;
}

__global__ void csr_fill(const int* __restrict__ ei, int* __restrict__ cursor,
                         int* __restrict__ csr) {
    int e = blockIdx.x * blockDim.x + threadIdx.x;
    if (e >= NE) return;
    int dst = ei[NE + e];
    int pos = atomicAdd(&cursor[dst], 1);
    csr[pos] = ei[e];
}

// ---------------- HMMA GEMM v4: 128-row blocks, warp tile 32 rows x 64 cols ----------------
// 8 warps: rowg = w>>1 (0..3) -> rows rowg*32..+31; colh = w&1 -> cols colh*64..+63.
// Per k-step per warp: 2 A-ldmatrix.x4 + 4 B-ldmatrix.x4 feeding 16 MMAs
// (B fragment bytes per output element ~40% lower than v3's 16x64 tile).
#define XS_STRIDE 68

__device__ __forceinline__ void mma16816(float* d, uint a0, uint a1, uint a2, uint a3,
                                         uint b0, uint b1) {
    asm volatile(
        "mma.sync.aligned.m16n8k16.row.col.f32.bf16.bf16.f32 "
        "{%0,%1,%2,%3}, {%4,%5,%6,%7}, {%8,%9}, {%0,%1,%2,%3};"
        : "+f"(d[0]), "+f"(d[1]), "+f"(d[2]), "+f"(d[3])
        : "r"(a0), "r"(a1), "r"(a2), "r"(a3), "r"(b0), "r"(b1));
}

__device__ __forceinline__ void ldmat_x4(uint& r0, uint& r1, uint& r2, uint& r3, uint saddr) {
    asm volatile("ldmatrix.sync.aligned.m8n8.x4.shared.b16 {%0,%1,%2,%3}, [%4];"
                 : "=r"(r0), "=r"(r1), "=r"(r2), "=r"(r3) : "r"(saddr));
}

__global__ void __launch_bounds__(256, 3)
gemm_mma(const uint* __restrict__ xb, const __nv_bfloat16* __restrict__ wtb,
         const int* __restrict__ cnt, uint* __restrict__ out) {
    __shared__ uint xs[128 * XS_STRIDE];
    __shared__ uint ws[128 * XS_STRIDE];

    const int t = threadIdx.x;
    const int row0 = blockIdx.x * 128;

    const uint4* x4 = reinterpret_cast<const uint4*>(xb);
    const uint4* w4 = reinterpret_cast<const uint4*>(wtb);
    #pragma unroll
    for (int c = t; c < 2048; c += 256) {
        int r = c >> 4, q = c & 15;
        uint4 v = make_uint4(0, 0, 0, 0);
        if (row0 + r < NN) v = x4[(size_t)(row0 + r) * 16 + q];
        *reinterpret_cast<uint4*>(&xs[r * XS_STRIDE + q * 4]) = v;
        *reinterpret_cast<uint4*>(&ws[r * XS_STRIDE + q * 4]) = w4[(size_t)r * 16 + q];
    }
    __syncthreads();

    const int w    = t >> 5;
    const int lane = t & 31;
    const int grp  = lane >> 2;
    const int tid  = lane & 3;
    const int rowg = w >> 1;       // 0..3: rows rowg*32..+31
    const int colh = w & 1;        // 0..1: cols colh*64..+63

    float d0[8][4], d1[8][4];      // m-tile 0 (rows +0..15), m-tile 1 (rows +16..31)
    #pragma unroll
    for (int nb = 0; nb < 8; nb++)
        #pragma unroll
        for (int q = 0; q < 4; q++) { d0[nb][q] = 0.f; d1[nb][q] = 0.f; }

    // ldmatrix lane->address mapping (same as v3)
    int arow  = rowg * 32 + (lane & 7) + ((lane >> 3) & 1) * 8;
    uint aoff = ((lane >> 4) & 1) * 4;
    uint addrA0 = (uint)__cvta_generic_to_shared(&xs[arow * XS_STRIDE + aoff]);
    uint addrA1 = addrA0 + (uint)(16 * XS_STRIDE * 4);
    int brow  = colh * 64 + ((lane >> 4) & 1) * 8 + (lane & 7);
    uint boff = ((lane >> 3) & 1) * 4;
    uint addrB = (uint)__cvta_generic_to_shared(&ws[brow * XS_STRIDE + boff]);

    #pragma unroll
    for (int kb = 0; kb < 8; kb++) {
        uint a00, a01, a02, a03, a10, a11, a12, a13;
        ldmat_x4(a00, a01, a02, a03, addrA0 + kb * 32);
        ldmat_x4(a10, a11, a12, a13, addrA1 + kb * 32);
        #pragma unroll
        for (int nbp = 0; nbp < 4; nbp++) {
            uint b00, b01, b10, b11;
            ldmat_x4(b00, b01, b10, b11,
                     addrB + (uint)(nbp * 16 * XS_STRIDE * 4) + kb * 32);
            mma16816(d0[nbp * 2],     a00, a01, a02, a03, b00, b01);
            mma16816(d0[nbp * 2 + 1], a00, a01, a02, a03, b10, b11);
            mma16816(d1[nbp * 2],     a10, a11, a12, a13, b00, b01);
            mma16816(d1[nbp * 2 + 1], a10, a11, a12, a13, b10, b11);
        }
    }

    // epilogue: two m-tiles
    #pragma unroll
    for (int mt = 0; mt < 2; mt++) {
        float (*d)[4] = mt ? d1 : d0;
        int r0 = row0 + rowg * 32 + mt * 16 + grp;
        int r1 = r0 + 8;
        float dv0 = (r0 < NN) ? rsqrtf((float)cnt[r0] + 2.0f) : 0.f;
        float dv1 = (r1 < NN) ? rsqrtf((float)cnt[r1] + 2.0f) : 0.f;
        #pragma unroll
        for (int nb = 0; nb < 8; nb++) {
            int cu = colh * 32 + nb * 4 + tid;
            if (r0 < NN) out[(size_t)r0 * 64 + cu] = pk_bf16x2(d[nb][0] * dv0, d[nb][1] * dv0);
            if (r1 < NN) out[(size_t)r1 * 64 + cu] = pk_bf16x2(d[nb][2] * dv1, d[nb][3] * dv1);
        }
    }
}

// ---------------- gather + combine (exact R6/R9/R10/R11 version) ----------------
#define ACC8(v)                                              \
    acc[0] += __uint_as_float((v).x << 16);                  \
    acc[1] += __uint_as_float((v).x & 0xffff0000u);          \
    acc[2] += __uint_as_float((v).y << 16);                  \
    acc[3] += __uint_as_float((v).y & 0xffff0000u);          \
    acc[4] += __uint_as_float((v).z << 16);                  \
    acc[5] += __uint_as_float((v).z & 0xffff0000u);          \
    acc[6] += __uint_as_float((v).w << 16);                  \
    acc[7] += __uint_as_float((v).w & 0xffff0000u);

__global__ void gather_combine(const int* __restrict__ rowptr, const int* __restrict__ csr,
                               const uint* __restrict__ g, const float* __restrict__ dinv,
                               const float* __restrict__ bias, uint* __restrict__ out) {
    int n = (blockIdx.x * blockDim.x + threadIdx.x) >> 5;
    if (n >= NN) return;
    int lane = threadIdx.x & 31;
    int half = lane >> 4;
    int hl   = lane & 15;
    int start = rowptr[n];
    int end   = rowptr[n + 1];

    const uint4* g4 = reinterpret_cast<const uint4*>(g);

    float acc[8];
    #pragma unroll
    for (int i = 0; i < 8; i++) acc[i] = 0.f;

    for (int base = start; base < end; base += 32) {
        int m = min(32, end - base);
        int s = (lane < m) ? csr[base + lane] : 0;
        int j = 0;
        for (; j + 2 <= m; j += 2) {
            int s0 = __shfl_sync(0xffffffffu, s, j + half);
            uint4 v = g4[(size_t)s0 * 16 + hl];
            ACC8(v)
        }
        if (j < m) {
            int s0 = __shfl_sync(0xffffffffu, s, m - 1);
            if (half == 0) {
                uint4 v = g4[(size_t)s0 * 16 + hl];
                ACC8(v)
            }
        }
    }

    #pragma unroll
    for (int i = 0; i < 8; i++)
        acc[i] += __shfl_xor_sync(0xffffffffu, acc[i], 16);

    if (half == 0) {
        float dv = dinv[n];
        uint4 sv = g4[(size_t)n * 16 + hl];
        float s0 = __uint_as_float(sv.x << 16), s1 = __uint_as_float(sv.x & 0xffff0000u);
        float s2 = __uint_as_float(sv.y << 16), s3 = __uint_as_float(sv.y & 0xffff0000u);
        float s4 = __uint_as_float(sv.z << 16), s5 = __uint_as_float(sv.z & 0xffff0000u);
        float s6 = __uint_as_float(sv.w << 16), s7 = __uint_as_float(sv.w & 0xffff0000u);
        const float4* b4 = reinterpret_cast<const float4*>(bias);
        float4 b0 = b4[hl * 2], b1 = b4[hl * 2 + 1];
        float r0 = fmaxf(dv * (acc[0] + 2.f * s0) + b0.x, 0.f);
        float r1 = fmaxf(dv * (acc[1] + 2.f * s1) + b0.y, 0.f);
        float r2 = fmaxf(dv * (acc[2] + 2.f * s2) + b0.z, 0.f);
        float r3 = fmaxf(dv * (acc[3] + 2.f * s3) + b0.w, 0.f);
        float r4 = fmaxf(dv * (acc[4] + 2.f * s4) + b1.x, 0.f);
        float r5 = fmaxf(dv * (acc[5] + 2.f * s5) + b1.y, 0.f);
        float r6 = fmaxf(dv * (acc[6] + 2.f * s6) + b1.z, 0.f);
        float r7 = fmaxf(dv * (acc[7] + 2.f * s7) + b1.w, 0.f);
        reinterpret_cast<uint4*>(out)[(size_t)n * 16 + hl] =
            make_uint4(pk_bf16x2(r0, r1), pk_bf16x2(r2, r3),
                       pk_bf16x2(r4, r5), pk_bf16x2(r6, r7));
    }
}

// ---------------- pooling (bf16 x) with fused per-graph counting ----------------
__global__ void pool_kernel(const uint* __restrict__ x, const int* __restrict__ batch,
                            float* __restrict__ gsum, float* __restrict__ gcnt) {
    int f  = threadIdx.x;
    int n0 = blockIdx.x * 64;
    if (n0 >= NN) return;
    int nend = min(n0 + 64, NN);
    int cur = batch[n0];
    float acc = 0.f, cacc = 0.f;
    for (int n = n0; n < nend; n++) {
        int b = batch[n];
        if (b != cur) {
            atomicAdd(&gsum[cur * F + f], acc);
            if (f == 0) atomicAdd(&gcnt[cur], cacc);
            acc = 0.f; cacc = 0.f; cur = b;
        }
        uint v = x[(size_t)n * 64 + (f >> 1)];
        acc += __uint_as_float((f & 1) ? (v & 0xffff0000u) : (v << 16));
        cacc += 1.f;
    }
    atomicAdd(&gsum[cur * F + f], acc);
    if (f == 0) atomicAdd(&gcnt[cur], cacc);
}

// ---------------- MLP head ----------------
__global__ void head_kernel(const float* __restrict__ gsum, const float* __restrict__ gcnt,
                            const float* __restrict__ fc1w, const float* __restrict__ fc1b,
                            const float* __restrict__ fc2w, const float* __restrict__ fc2b,
                            float* __restrict__ out) {
    int gI = blockIdx.x;
    int f  = threadIdx.x;
    __shared__ float pooled[F];
    __shared__ float red[F];
    float cnt = fmaxf(gcnt[gI], 1.0f);
    pooled[f] = gsum[gI * F + f] / cnt;
    __syncthreads();
    float a = fc1b[f];
    #pragma unroll 8
    for (int k = 0; k < F; k++) a += pooled[k] * fc1w[k * F + f];
    red[f] = fmaxf(a, 0.f) * fc2w[f];
    __syncthreads();
    #pragma unroll
    for (int s = 64; s > 0; s >>= 1) {
        if (f < s) red[f] += red[f + s];
        __syncthreads();
    }
    if (f == 0) out[gI] = red[0] + fc2b[0];
}

// ---------------- launch: serial R11 structure, gemm v4 ----------------
extern "C" void kernel_launch(void* const* d_in, const int* in_sizes, int n_in,
                              void* d_out, int out_size) {
    const float* x      = (const float*)d_in[0];
    const int*   ei     = (const int*)d_in[1];
    const int*   batch  = (const int*)d_in[2];
    const float* conv_w = (const float*)d_in[4];
    const float* conv_b = (const float*)d_in[5];
    const float* fc1w   = (const float*)d_in[6];
    const float* fc1b   = (const float*)d_in[7];
    const float* fc2w   = (const float*)d_in[8];
    const float* fc2b   = (const float*)d_in[9];
    float* out = (float*)d_out;

    float *dinv, *gsum, *gcnt;
    uint *xb, *bufA, *stat;
    __nv_bfloat16* wtb;
    int *cnt, *rowptr, *cursor, *csr;
    cudaGetSymbolAddress((void**)&xb,     g_xb);
    cudaGetSymbolAddress((void**)&bufA,   g_bufA);
    cudaGetSymbolAddress((void**)&wtb,    g_wtb);
    cudaGetSymbolAddress((void**)&cnt,    g_cnt);
    cudaGetSymbolAddress((void**)&rowptr, g_rowptr);
    cudaGetSymbolAddress((void**)&cursor, g_cursor);
    cudaGetSymbolAddress((void**)&csr,    g_csr);
    cudaGetSymbolAddress((void**)&stat,   g_stat);
    cudaGetSymbolAddress((void**)&dinv,   g_dinv);
    cudaGetSymbolAddress((void**)&gsum,   g_gsum);
    cudaGetSymbolAddress((void**)&gcnt,   g_gcnt);

    const int GEMM_GRID = (NN + 127) / 128;   // 782
    const int CONV_N = NN * (F / 2) + NCONV * F * F;

    // gemm L0 at absolute launch #4 (the slot ncu captures).
    fill_init<<<(NN + 255) / 256, 256>>>(cnt, stat, gsum, gcnt);              // 1
    count_kernel<<<(NE + 255) / 256, 256>>>(ei, cnt);                         // 2
    convert_all<<<(CONV_N + 255) / 256, 256>>>(x, conv_w, xb, wtb);           // 3
    gemm_mma<<<GEMM_GRID, 256>>>(xb, wtb, cnt, bufA);                         // 4 (profiled)
    scan_lb<<<NB_SCAN, 1024>>>(cnt, rowptr, dinv, cursor, stat);              // 5
    csr_fill<<<(NE + 255) / 256, 256>>>(ei, cursor, csr);                     // 6
    gather_combine<<<(NN * 32 + 255) / 256, 256>>>(rowptr, csr, bufA, dinv, conv_b, xb); // 7

    for (int l = 1; l < NCONV; l++) {
        gemm_mma<<<GEMM_GRID, 256>>>(xb, wtb + (size_t)l * F * F, cnt, bufA);
        gather_combine<<<(NN * 32 + 255) / 256, 256>>>(rowptr, csr, bufA, dinv,
                                                       conv_b + (size_t)l * F, xb);
    }

    // global mean pool (gcnt fused) + head
    pool_kernel<<<(NN + 63) / 64, 128>>>(xb, batch, gsum, gcnt);
    head_kernel<<<NG, 128>>>(gsum, gcnt, fc1w, fc1b, fc2w, fc2b, out);
}

// round 15
// speedup vs baseline: 1.0726x; 1.0726x over previous
#include <cuda_runtime.h>
#include <cuda_bf16.h>

#define NN 100000
#define NE 1600000
#define NG 512
#define F  128
#define NCONV 4
#define NB_SCAN 98   // (NN + 1023) / 1024

typedef unsigned int uint;

// ---------------- scratch (device globals; no allocation) ----------------
__device__ uint  g_xb[NN * (F / 2)];     // layer input x, packed bf16x2 (25.6MB)
__device__ uint  g_bufA[NN * (F / 2)];   // g = (x@W)*dinv[row], packed bf16x2
__device__ __nv_bfloat16 g_wtb[NCONV * F * F];  // W^T per layer, [l][c][k] bf16
__device__ int   g_cnt[NN];
__device__ int   g_rowptr[NN + 1];
__device__ int   g_cursor[NN];
__device__ int   g_csr[NE];
__device__ uint  g_stat[128];            // decoupled-lookback status words
__device__ float g_dinv[NN];
__device__ float g_gsum[NG * F];
__device__ float g_gcnt[NG];

// ---------------- init: zero cnt + scan flags + pool accumulators ----------------
__global__ void fill_init(int* __restrict__ cnt, uint* __restrict__ stat,
                          float* __restrict__ gsum, float* __restrict__ gcnt) {
    int i = blockIdx.x * blockDim.x + threadIdx.x;
    if (i < NN) cnt[i] = 0;
    if (i < 128) stat[i] = 0u;
    if (i < NG * F) gsum[i] = 0.f;
    if (i < NG) gcnt[i] = 0.f;
}

__global__ void count_kernel(const int* __restrict__ ei, int* __restrict__ cnt) {
    int e = blockIdx.x * blockDim.x + threadIdx.x;
    if (e < NE) atomicAdd(&cnt[ei[NE + e]], 1);
}

__device__ __forceinline__ uint pk_bf16x2(float lo, float hi) {
    uint r;
    asm("cvt.rn.bf16x2.f32 %0, %1, %2;" : "=r"(r) : "f"(hi), "f"(lo));
    return r;
}

// W -> W^T bf16 only (x conversion fused into gemm0)
__global__ void convert_w(const float* __restrict__ W, __nv_bfloat16* __restrict__ wtb) {
    int j = blockIdx.x * blockDim.x + threadIdx.x;
    if (j < NCONV * F * F) {
        int l = j >> 14, r = j & 16383, c = r >> 7, k = r & 127;
        wtb[j] = __float2bfloat16(W[(l << 14) + (k << 7) + c]);
    }
}

// ---------------- single-pass scan (decoupled lookback) + dinv + cursor ----------------
__global__ void scan_lb(const int* __restrict__ cnt, int* __restrict__ rowptr,
                        float* __restrict__ dinv, int* __restrict__ cursor,
                        uint* __restrict__ stat) {
    __shared__ int s[1024];
    __shared__ int s_prefix;
    int bid = blockIdx.x;
    int tid = threadIdx.x;
    int i = bid * 1024 + tid;
    int v = (i < NN) ? cnt[i] : 0;
    if (i < NN) dinv[i] = rsqrtf((float)v + 2.0f);   // improved=True self-loop weight 2
    s[tid] = v;
    __syncthreads();
    #pragma unroll
    for (int off = 1; off < 1024; off <<= 1) {
        int t = (tid >= off) ? s[tid - off] : 0;
        __syncthreads();
        s[tid] += t;
        __syncthreads();
    }
    if (tid == 1023) {
        uint agg = (uint)s[1023];
        atomicExch(&stat[bid], agg | ((bid == 0 ? 2u : 1u) << 30));
    }
    if (bid == 0 && tid == 0) s_prefix = 0;
    if (bid > 0 && tid < 32) {
        int lane = tid;
        uint run = 0;
        int p = bid - 1;
        while (true) {
            int idx = p - lane;
            uint wv;
            if (idx >= 0) {
                do { wv = atomicAdd(&stat[idx], 0u); } while ((wv >> 30) == 0u);
            } else {
                wv = (2u << 30);
            }
            uint m2 = __ballot_sync(0xffffffffu, (wv >> 30) == 2u);
            if (m2) {
                int firstp = __ffs(m2) - 1;
                uint val = (lane <= firstp) ? (wv & 0x3fffffffu) : 0u;
                #pragma unroll
                for (int o = 16; o > 0; o >>= 1) val += __shfl_down_sync(0xffffffffu, val, o);
                if (lane == 0) run += val;
                break;
            } else {
                uint val = wv & 0x3fffffffu;
                #pragma unroll
                for (int o = 16; o > 0; o >>= 1) val += __shfl_down_sync(0xffffffffu, val, o);
                if (lane == 0) run += val;
                p -= 32;
            }
        }
        if (lane == 0) {
            s_prefix = (int)run;
            atomicExch(&stat[bid], (run + (uint)s[1023]) | (2u << 30));
        }
    }
    __syncthreads();
    int pre = s_prefix;
    if (i < NN) {
        int incl = pre + s[tid];
        rowptr[i + 1] = incl;
        cursor[i] = incl - v;
    }
    if (i == 0) rowptr[0] = 0;
}

__global__ void csr_fill(const int* __restrict__ ei, int* __restrict__ cursor,
                         int* __restrict__ csr) {
    int e = blockIdx.x * blockDim.x + threadIdx.x;
    if (e >= NE) return;
    int dst = ei[NE + e];
    int pos = atomicAdd(&cursor[dst], 1);
    csr[pos] = ei[e];
}

// ---------------- HMMA GEMM v3 core (exact R11 mainloop + epilogue) ----------------
#define XS_STRIDE 68

__device__ __forceinline__ void mma16816(float* d, uint a0, uint a1, uint a2, uint a3,
                                         uint b0, uint b1) {
    asm volatile(
        "mma.sync.aligned.m16n8k16.row.col.f32.bf16.bf16.f32 "
        "{%0,%1,%2,%3}, {%4,%5,%6,%7}, {%8,%9}, {%0,%1,%2,%3};"
        : "+f"(d[0]), "+f"(d[1]), "+f"(d[2]), "+f"(d[3])
        : "r"(a0), "r"(a1), "r"(a2), "r"(a3), "r"(b0), "r"(b1));
}

__device__ __forceinline__ void ldmat_x4(uint& r0, uint& r1, uint& r2, uint& r3, uint saddr) {
    asm volatile("ldmatrix.sync.aligned.m8n8.x4.shared.b16 {%0,%1,%2,%3}, [%4];"
                 : "=r"(r0), "=r"(r1), "=r"(r2), "=r"(r3) : "r"(saddr));
}

__device__ __forceinline__ void mma_core_v3(const uint* xs, const uint* ws, int row0,
                                            const int* __restrict__ cnt,
                                            uint* __restrict__ out, int t) {
    const int w    = t >> 5;
    const int lane = t & 31;
    const int grp  = lane >> 2;
    const int tid  = lane & 3;
    const int rowg = w >> 1;
    const int colh = w & 1;

    float d[8][4];
    #pragma unroll
    for (int nb = 0; nb < 8; nb++)
        #pragma unroll
        for (int q = 0; q < 4; q++) d[nb][q] = 0.f;

    int arow  = rowg * 16 + (lane & 7) + ((lane >> 3) & 1) * 8;
    uint aoff = ((lane >> 4) & 1) * 4;
    uint addrA = (uint)__cvta_generic_to_shared(&xs[arow * XS_STRIDE + aoff]);
    int brow  = colh * 64 + ((lane >> 4) & 1) * 8 + (lane & 7);
    uint boff = ((lane >> 3) & 1) * 4;
    uint addrB = (uint)__cvta_generic_to_shared(&ws[brow * XS_STRIDE + boff]);

    #pragma unroll
    for (int kb = 0; kb < 8; kb++) {
        uint a0, a1, a2, a3;
        ldmat_x4(a0, a1, a2, a3, addrA + kb * 32);
        #pragma unroll
        for (int nbp = 0; nbp < 4; nbp++) {
            uint b00, b01, b10, b11;
            ldmat_x4(b00, b01, b10, b11,
                     addrB + (uint)(nbp * 16 * XS_STRIDE * 4) + kb * 32);
            mma16816(d[nbp * 2],     a0, a1, a2, a3, b00, b01);
            mma16816(d[nbp * 2 + 1], a0, a1, a2, a3, b10, b11);
        }
    }

    int r0 = row0 + rowg * 16 + grp;
    int r1 = r0 + 8;
    float dv0 = (r0 < NN) ? rsqrtf((float)cnt[r0] + 2.0f) : 0.f;
    float dv1 = (r1 < NN) ? rsqrtf((float)cnt[r1] + 2.0f) : 0.f;
    #pragma unroll
    for (int nb = 0; nb < 8; nb++) {
        int cu = colh * 32 + nb * 4 + tid;
        if (r0 < NN) out[(size_t)r0 * 64 + cu] = pk_bf16x2(d[nb][0] * dv0, d[nb][1] * dv0);
        if (r1 < NN) out[(size_t)r1 * 64 + cu] = pk_bf16x2(d[nb][2] * dv1, d[nb][3] * dv1);
    }
}

// gemm0: x read directly as fp32, converted to bf16 while staging to smem
__global__ void __launch_bounds__(256, 4)
gemm_mma_f32(const float* __restrict__ x, const __nv_bfloat16* __restrict__ wtb,
             const int* __restrict__ cnt, uint* __restrict__ out) {
    __shared__ uint xs[64 * XS_STRIDE];
    __shared__ uint ws[128 * XS_STRIDE];

    const int t = threadIdx.x;
    const int row0 = blockIdx.x * 64;

    const float4* xf = reinterpret_cast<const float4*>(x);
    const uint4* w4 = reinterpret_cast<const uint4*>(wtb);
    #pragma unroll
    for (int c = t; c < 1024; c += 256) {          // 64 rows x 16 bf16x2-uint4 chunks
        int r = c >> 4, q = c & 15;
        uint4 v = make_uint4(0, 0, 0, 0);
        if (row0 + r < NN) {
            float4 f0 = xf[(size_t)(row0 + r) * 32 + q * 2];
            float4 f1 = xf[(size_t)(row0 + r) * 32 + q * 2 + 1];
            v = make_uint4(pk_bf16x2(f0.x, f0.y), pk_bf16x2(f0.z, f0.w),
                           pk_bf16x2(f1.x, f1.y), pk_bf16x2(f1.z, f1.w));
        }
        *reinterpret_cast<uint4*>(&xs[r * XS_STRIDE + q * 4]) = v;
    }
    #pragma unroll
    for (int c = t; c < 2048; c += 256) {
        int r = c >> 4, q = c & 15;
        *reinterpret_cast<uint4*>(&ws[r * XS_STRIDE + q * 4]) = w4[(size_t)r * 16 + q];
    }
    __syncthreads();
    mma_core_v3(xs, ws, row0, cnt, out, t);
}

// gemm layers 1..3: x from bf16 xb (exact R11)
__global__ void __launch_bounds__(256, 4)
gemm_mma(const uint* __restrict__ xb, const __nv_bfloat16* __restrict__ wtb,
         const int* __restrict__ cnt, uint* __restrict__ out) {
    __shared__ uint xs[64 * XS_STRIDE];
    __shared__ uint ws[128 * XS_STRIDE];

    const int t = threadIdx.x;
    const int row0 = blockIdx.x * 64;

    const uint4* x4 = reinterpret_cast<const uint4*>(xb);
    const uint4* w4 = reinterpret_cast<const uint4*>(wtb);
    #pragma unroll
    for (int c = t; c < 1024; c += 256) {
        int r = c >> 4, q = c & 15;
        uint4 v = make_uint4(0, 0, 0, 0);
        if (row0 + r < NN) v = x4[(size_t)(row0 + r) * 16 + q];
        *reinterpret_cast<uint4*>(&xs[r * XS_STRIDE + q * 4]) = v;
    }
    #pragma unroll
    for (int c = t; c < 2048; c += 256) {
        int r = c >> 4, q = c & 15;
        *reinterpret_cast<uint4*>(&ws[r * XS_STRIDE + q * 4]) = w4[(size_t)r * 16 + q];
    }
    __syncthreads();
    mma_core_v3(xs, ws, row0, cnt, out, t);
}

// ---------------- gather + combine (exact R11) ----------------
#define ACC8(v)                                              \
    acc[0] += __uint_as_float((v).x << 16);                  \
    acc[1] += __uint_as_float((v).x & 0xffff0000u);          \
    acc[2] += __uint_as_float((v).y << 16);                  \
    acc[3] += __uint_as_float((v).y & 0xffff0000u);          \
    acc[4] += __uint_as_float((v).z << 16);                  \
    acc[5] += __uint_as_float((v).z & 0xffff0000u);          \
    acc[6] += __uint_as_float((v).w << 16);                  \
    acc[7] += __uint_as_float((v).w & 0xffff0000u);

__global__ void gather_combine(const int* __restrict__ rowptr, const int* __restrict__ csr,
                               const uint* __restrict__ g, const float* __restrict__ dinv,
                               const float* __restrict__ bias, uint* __restrict__ out) {
    int n = (blockIdx.x * blockDim.x + threadIdx.x) >> 5;
    if (n >= NN) return;
    int lane = threadIdx.x & 31;
    int half = lane >> 4;
    int hl   = lane & 15;
    int start = rowptr[n];
    int end   = rowptr[n + 1];

    const uint4* g4 = reinterpret_cast<const uint4*>(g);

    float acc[8];
    #pragma unroll
    for (int i = 0; i < 8; i++) acc[i] = 0.f;

    for (int base = start; base < end; base += 32) {
        int m = min(32, end - base);
        int s = (lane < m) ? csr[base + lane] : 0;
        int j = 0;
        for (; j + 2 <= m; j += 2) {
            int s0 = __shfl_sync(0xffffffffu, s, j + half);
            uint4 v = g4[(size_t)s0 * 16 + hl];
            ACC8(v)
        }
        if (j < m) {
            int s0 = __shfl_sync(0xffffffffu, s, m - 1);
            if (half == 0) {
                uint4 v = g4[(size_t)s0 * 16 + hl];
                ACC8(v)
            }
        }
    }

    #pragma unroll
    for (int i = 0; i < 8; i++)
        acc[i] += __shfl_xor_sync(0xffffffffu, acc[i], 16);

    if (half == 0) {
        float dv = dinv[n];
        uint4 sv = g4[(size_t)n * 16 + hl];
        float s0 = __uint_as_float(sv.x << 16), s1 = __uint_as_float(sv.x & 0xffff0000u);
        float s2 = __uint_as_float(sv.y << 16), s3 = __uint_as_float(sv.y & 0xffff0000u);
        float s4 = __uint_as_float(sv.z << 16), s5 = __uint_as_float(sv.z & 0xffff0000u);
        float s6 = __uint_as_float(sv.w << 16), s7 = __uint_as_float(sv.w & 0xffff0000u);
        const float4* b4 = reinterpret_cast<const float4*>(bias);
        float4 b0 = b4[hl * 2], b1 = b4[hl * 2 + 1];
        float r0 = fmaxf(dv * (acc[0] + 2.f * s0) + b0.x, 0.f);
        float r1 = fmaxf(dv * (acc[1] + 2.f * s1) + b0.y, 0.f);
        float r2 = fmaxf(dv * (acc[2] + 2.f * s2) + b0.z, 0.f);
        float r3 = fmaxf(dv * (acc[3] + 2.f * s3) + b0.w, 0.f);
        float r4 = fmaxf(dv * (acc[4] + 2.f * s4) + b1.x, 0.f);
        float r5 = fmaxf(dv * (acc[5] + 2.f * s5) + b1.y, 0.f);
        float r6 = fmaxf(dv * (acc[6] + 2.f * s6) + b1.z, 0.f);
        float r7 = fmaxf(dv * (acc[7] + 2.f * s7) + b1.w, 0.f);
        reinterpret_cast<uint4*>(out)[(size_t)n * 16 + hl] =
            make_uint4(pk_bf16x2(r0, r1), pk_bf16x2(r2, r3),
                       pk_bf16x2(r4, r5), pk_bf16x2(r6, r7));
    }
}

// ---------------- pooling (bf16 x) with fused per-graph counting ----------------
__global__ void pool_kernel(const uint* __restrict__ x, const int* __restrict__ batch,
                            float* __restrict__ gsum, float* __restrict__ gcnt) {
    int f  = threadIdx.x;
    int n0 = blockIdx.x * 64;
    if (n0 >= NN) return;
    int nend = min(n0 + 64, NN);
    int cur = batch[n0];
    float acc = 0.f, cacc = 0.f;
    for (int n = n0; n < nend; n++) {
        int b = batch[n];
        if (b != cur) {
            atomicAdd(&gsum[cur * F + f], acc);
            if (f == 0) atomicAdd(&gcnt[cur], cacc);
            acc = 0.f; cacc = 0.f; cur = b;
        }
        uint v = x[(size_t)n * 64 + (f >> 1)];
        acc += __uint_as_float((f & 1) ? (v & 0xffff0000u) : (v << 16));
        cacc += 1.f;
    }
    atomicAdd(&gsum[cur * F + f], acc);
    if (f == 0) atomicAdd(&gcnt[cur], cacc);
}

// ---------------- MLP head ----------------
__global__ void head_kernel(const float* __restrict__ gsum, const float* __restrict__ gcnt,
                            const float* __restrict__ fc1w, const float* __restrict__ fc1b,
                            const float* __restrict__ fc2w, const float* __restrict__ fc2b,
                            float* __restrict__ out) {
    int gI = blockIdx.x;
    int f  = threadIdx.x;
    __shared__ float pooled[F];
    __shared__ float red[F];
    float cnt = fmaxf(gcnt[gI], 1.0f);
    pooled[f] = gsum[gI * F + f] / cnt;
    __syncthreads();
    float a = fc1b[f];
    #pragma unroll 8
    for (int k = 0; k < F; k++) a += pooled[k] * fc1w[k * F + f];
    red[f] = fmaxf(a, 0.f) * fc2w[f];
    __syncthreads();
    #pragma unroll
    for (int s = 64; s > 0; s >>= 1) {
        if (f < s) red[f] += red[f + s];
        __syncthreads();
    }
    if (f == 0) out[gI] = red[0] + fc2b[0];
}

// ---------------- launch: R11 structure, gemm0 reads fp32 x directly ----------------
extern "C" void kernel_launch(void* const* d_in, const int* in_sizes, int n_in,
                              void* d_out, int out_size) {
    const float* x      = (const float*)d_in[0];
    const int*   ei     = (const int*)d_in[1];
    const int*   batch  = (const int*)d_in[2];
    const float* conv_w = (const float*)d_in[4];
    const float* conv_b = (const float*)d_in[5];
    const float* fc1w   = (const float*)d_in[6];
    const float* fc1b   = (const float*)d_in[7];
    const float* fc2w   = (const float*)d_in[8];
    const float* fc2b   = (const float*)d_in[9];
    float* out = (float*)d_out;

    float *dinv, *gsum, *gcnt;
    uint *xb, *bufA, *stat;
    __nv_bfloat16* wtb;
    int *cnt, *rowptr, *cursor, *csr;
    cudaGetSymbolAddress((void**)&xb,     g_xb);
    cudaGetSymbolAddress((void**)&bufA,   g_bufA);
    cudaGetSymbolAddress((void**)&wtb,    g_wtb);
    cudaGetSymbolAddress((void**)&cnt,    g_cnt);
    cudaGetSymbolAddress((void**)&rowptr, g_rowptr);
    cudaGetSymbolAddress((void**)&cursor, g_cursor);
    cudaGetSymbolAddress((void**)&csr,    g_csr);
    cudaGetSymbolAddress((void**)&stat,   g_stat);
    cudaGetSymbolAddress((void**)&dinv,   g_dinv);
    cudaGetSymbolAddress((void**)&gsum,   g_gsum);
    cudaGetSymbolAddress((void**)&gcnt,   g_gcnt);

    const int GEMM_GRID = (NN + 63) / 64;     // 1563

    // gemm0 at absolute launch #4 (the slot ncu captures).
    fill_init<<<(NN + 255) / 256, 256>>>(cnt, stat, gsum, gcnt);              // 1
    count_kernel<<<(NE + 255) / 256, 256>>>(ei, cnt);                         // 2
    convert_w<<<(NCONV * F * F + 255) / 256, 256>>>(conv_w, wtb);             // 3
    gemm_mma_f32<<<GEMM_GRID, 256>>>(x, wtb, cnt, bufA);                      // 4 (profiled)
    scan_lb<<<NB_SCAN, 1024>>>(cnt, rowptr, dinv, cursor, stat);              // 5
    csr_fill<<<(NE + 255) / 256, 256>>>(ei, cursor, csr);                     // 6
    gather_combine<<<(NN * 32 + 255) / 256, 256>>>(rowptr, csr, bufA, dinv, conv_b, xb); // 7

    for (int l = 1; l < NCONV; l++) {
        gemm_mma<<<GEMM_GRID, 256>>>(xb, wtb + (size_t)l * F * F, cnt, bufA);
        gather_combine<<<(NN * 32 + 255) / 256, 256>>>(rowptr, csr, bufA, dinv,
                                                       conv_b + (size_t)l * F, xb);
    }

    // global mean pool (gcnt fused) + head
    pool_kernel<<<(NN + 63) / 64, 128>>>(xb, batch, gsum, gcnt);
    head_kernel<<<NG, 128>>>(gsum, gcnt, fc1w, fc1b, fc2w, fc2b, out);
}